// round 17
// baseline (speedup 1.0000x reference)
#include <cuda_runtime.h>
#include <cstdint>

#define B_TOTAL 2097152
#define NPHI    128
#define NCOEF   64
#define EPT     4
#define TPB     256
#define TPB_COEF 1024

// 68 packed (re,im) monomial coefficients:
//  [s*9 + p]       p=0..8 : F_s(v)   (s index 0..3 -> s=1,3,5,7)
//  [36 + s*8 + p]  p=0..7 : G_s(v)   (stored PRE-DOUBLED: includes the 2 from sin2t)
__device__ unsigned long long g_coef[68];
__device__ unsigned g_flag;   // publication flag (stays 1 after first launch)

// Chebyshev->monomial tables: MC[q][p] = coeff of v^p in 2*cos(q*phi), v=2cos phi
__device__ __constant__ float MC[9][9] = {
    { 2, 0,  0, 0,  0, 0,  0, 0, 0},
    { 0, 1,  0, 0,  0, 0,  0, 0, 0},
    {-2, 0,  1, 0,  0, 0,  0, 0, 0},
    { 0,-3,  0, 1,  0, 0,  0, 0, 0},
    { 2, 0, -4, 0,  1, 0,  0, 0, 0},
    { 0, 5,  0,-5,  0, 1,  0, 0, 0},
    {-2, 0,  9, 0, -6, 0,  1, 0, 0},
    { 0,-7,  0,14,  0,-7,  0, 1, 0},
    { 2, 0,-16, 0, 20, 0, -8, 0, 1}};
// MU[k][p] = coeff of v^p in U_k(v) = sin((k+1)phi)/sin(phi)
__device__ __constant__ float MU[8][8] = {
    { 1, 0, 0, 0,  0, 0, 0, 0},
    { 0, 1, 0, 0,  0, 0, 0, 0},
    {-1, 0, 1, 0,  0, 0, 0, 0},
    { 0,-2, 0, 1,  0, 0, 0, 0},
    { 1, 0,-3, 0,  1, 0, 0, 0},
    { 0, 3, 0,-4,  0, 1, 0, 0},
    {-1, 0, 6, 0, -5, 0, 1, 0},
    { 0,-4, 0,10,  0,-6, 0, 1}};

// ---------------- f32x2 packed helpers ----------------
__device__ __forceinline__ unsigned long long pk2(float lo, float hi) {
    unsigned long long r;
    asm("mov.b64 %0, {%1, %2};" : "=l"(r) : "f"(lo), "f"(hi));
    return r;
}
__device__ __forceinline__ void upk2(unsigned long long v, float& lo, float& hi) {
    asm("mov.b64 {%0, %1}, %2;" : "=f"(lo), "=f"(hi) : "l"(v));
}
__device__ __forceinline__ unsigned long long fma2(unsigned long long a,
                                                   unsigned long long b,
                                                   unsigned long long c) {
    unsigned long long d;
    asm("fma.rn.f32x2 %0, %1, %2, %3;" : "=l"(d) : "l"(a), "l"(b), "l"(c));
    return d;
}
__device__ __forceinline__ unsigned long long mul2(unsigned long long a,
                                                   unsigned long long b) {
    unsigned long long d;
    asm("mul.rn.f32x2 %0, %1, %2;" : "=l"(d) : "l"(a), "l"(b));
    return d;
}

// ---------------- Kernel A: single-CTA log-depth tree (1024 threads) --------
// P = Rz0 * (W Rz1) * ... * (W Rz127). Node: A (=P00), C (=P10) Laurent coeff
// arrays, idx i <-> exponent 2i-n (n = #W factors). D = R A, B = -R C with
// (Rf)_m = conj(f_{-m}).
// 128 leaves, 7 merge levels, all local: __syncthreads between levels.
__global__ void __launch_bounds__(TPB_COEF, 1)
qsp_coef_kernel(const float* __restrict__ phis) {
    cudaTriggerProgrammaticLaunchCompletion();

    __shared__ float2 A0[256], C0[256], A1[256], C1[256];  // ping-pong levels
    __shared__ float2 Afin[128];
    __shared__ float2 alsh[NCOEF];
    __shared__ float2 Cc[9][4], Dd[8][4];

    int t = threadIdx.x;

    // ---- leaves (stride 2): leaf g at A0[2g..2g+1] ----
    if (t < NPHI) {
        float s, c;
        sincosf(phis[t], &s, &c);
        if (t == 0) {
            A0[0] = make_float2(c, s);             // Rz0: n=0, A=[e0]
            A0[1] = make_float2(0.f, 0.f);
            C0[0] = make_float2(0.f, 0.f);
            C0[1] = make_float2(0.f, 0.f);
        } else {
            float hc = 0.5f * c, hs = 0.5f * s;
            A0[2 * t]     = make_float2(hc, hs);   // exp -1
            A0[2 * t + 1] = make_float2(hc, hs);   // exp +1
            C0[2 * t]     = make_float2(-hc, -hs);
            C0[2 * t + 1] = make_float2(hc, hs);
        }
    }
    __syncthreads();

    // ---- levels 0..5: 64->32->16->8->4->2 nodes ----
    float2 *Ain = A0, *Cin = C0, *Aout = A1, *Cout = C1;
#pragma unroll
    for (int lev = 0; lev < 6; lev++) {
        int half = 1 << lev, Sin = half + 1, Sout = 2 * half + 1;
        int nodes = 64 >> lev;        // output nodes this level
        int total = nodes * 2 * Sout;
        for (int task = t; task < total; task += TPB_COEF) {
            int node  = task / (2 * Sout);
            int rem   = task - node * (2 * Sout);
            int entry = rem / Sout;
            int tt    = rem - entry * Sout;
            int n1 = half - (node == 0);   // node 0 holds leaf 0 (one fewer W)
            int n2 = half;
            if (tt > n1 + n2) continue;
            const float2* A1p = Ain + (2 * node) * Sin;
            const float2* C1p = Cin + (2 * node) * Sin;
            const float2* A2p = Ain + (2 * node + 1) * Sin;
            const float2* C2p = Cin + (2 * node + 1) * Sin;
            int ilo = tt - n2; if (ilo < 0) ilo = 0;
            int ihi = tt < n1 ? tt : n1;
            float sr = 0.f, si = 0.f;
            if (entry == 0) {
                // A'' = A1*A2 + B1*C2, B1[i] = -conj(C1[n1-i])
                for (int i = ilo; i <= ihi; i++) {
                    float2 a1 = A1p[i], cr = C1p[n1 - i];
                    float2 a2 = A2p[tt - i], c2 = C2p[tt - i];
                    float br = -cr.x, bi = cr.y;
                    sr += a1.x * a2.x - a1.y * a2.y + br * c2.x - bi * c2.y;
                    si += a1.x * a2.y + a1.y * a2.x + br * c2.y + bi * c2.x;
                }
                Aout[node * Sout + tt] = make_float2(sr, si);
            } else {
                // C'' = C1*A2 + D1*C2, D1[i] = conj(A1[n1-i])
                for (int i = ilo; i <= ihi; i++) {
                    float2 c1 = C1p[i], ar = A1p[n1 - i];
                    float2 a2 = A2p[tt - i], c2 = C2p[tt - i];
                    float dr = ar.x, di = -ar.y;
                    sr += c1.x * a2.x - c1.y * a2.y + dr * c2.x - di * c2.y;
                    si += c1.x * a2.y + c1.y * a2.x + dr * c2.y + di * c2.x;
                }
                Cout[node * Sout + tt] = make_float2(sr, si);
            }
        }
        __syncthreads();
        float2* tmp;
        tmp = Ain; Ain = Aout; Aout = tmp;
        tmp = Cin; Cin = Cout; Cout = tmp;
    }

    // ---- top level: 2 nodes (stride 65) -> final A only (len 128) ----
    // 8 threads per output coefficient, strided dot + width-8 shfl reduce.
    {
        int n1 = 63, n2 = 64;
        const float2* A1p = Ain;            // left node (contains leaf 0)
        const float2* C1p = Cin;
        const float2* A2p = Ain + 65;
        const float2* C2p = Cin + 65;
        int o  = t >> 3;                    // 0..127
        int sl = t & 7;
        int ilo = o - n2; if (ilo < 0) ilo = 0;
        int ihi = o < n1 ? o : n1;
        float sr = 0.f, si = 0.f;
        for (int i = ilo + sl; i <= ihi; i += 8) {
            float2 a1 = A1p[i], cr = C1p[n1 - i];
            float2 a2 = A2p[o - i], c2 = C2p[o - i];
            float br = -cr.x, bi = cr.y;
            sr += a1.x * a2.x - a1.y * a2.y + br * c2.x - bi * c2.y;
            si += a1.x * a2.y + a1.y * a2.x + br * c2.y + bi * c2.x;
        }
#pragma unroll
        for (int d = 4; d; d >>= 1) {
            sr += __shfl_down_sync(0xffffffffu, sr, d, 8);
            si += __shfl_down_sync(0xffffffffu, si, d, 8);
        }
        if (sl == 0) Afin[o] = make_float2(sr, si);
    }
    __syncthreads();

    // ---- tail: al -> regroup -> monomial -> g_coef -> flag ----
    if (t < NCOEF) {
        // exp 2t+1 -> idx t+64 ; exp -(2t+1) -> idx 63-t
        float2 p = Afin[t + 64], q = Afin[63 - t];
        alsh[t] = make_float2(p.x + q.x, p.y + q.y);
    }
    __syncthreads();

    if (t < 36) {
        int q = t >> 2, sidx = t & 3;
        float2 aP = make_float2(0.f, 0.f), aM = make_float2(0.f, 0.f);
        if (q <= 7) aP = alsh[8 * q + sidx];
        if (q >= 1) aM = alsh[8 * q - sidx - 1];
        Cc[q][sidx] = make_float2(aP.x + aM.x, aP.y + aM.y);
        if (q >= 1) Dd[q - 1][sidx] = make_float2(aM.x - aP.x, aM.y - aP.y);
    }
    __syncthreads();

    if (t < 36) {
        int p = t >> 2, sidx = t & 3;
        float re = 0.f, im = 0.f;
#pragma unroll
        for (int q = 0; q < 9; q++) {
            float mc = MC[q][p];
            re += Cc[q][sidx].x * mc;
            im += Cc[q][sidx].y * mc;
        }
        g_coef[sidx * 9 + p] = pk2(0.5f * re, 0.5f * im);
    } else if (t >= 64 && t < 96) {
        int tt = t - 64;
        int p = tt >> 2, sidx = tt & 3;
        float re = 0.f, im = 0.f;
#pragma unroll
        for (int k = 0; k < 8; k++) {
            float mu = MU[k][p];
            re += Dd[k][sidx].x * mu;
            im += Dd[k][sidx].y * mu;
        }
        // G stored PRE-DOUBLED: absorbs the factor 2 of sin(2t)=2 sin cos.
        g_coef[36 + sidx * 8 + p] = pk2(2.0f * re, 2.0f * im);
    }
    __syncthreads();
    if (t == 0) {
        __threadfence();
        asm volatile("st.global.release.gpu.u32 [%0], %1;"
                     :: "l"(&g_flag), "r"(1u) : "memory");
    }
}

// ---------------- Kernel B: per-element eval (smem coefficients) -----------
// S = sum_s cos(s th) F_s(v) + sin(s th) sin(16 th) G_s(v),  v = 2cos(16 th)
// Prework computed f32x2-PACKED across element pairs; negations via sign-bit
// XOR on the idle alu pipe. (Identical to the round-16 validated eval.)
__global__ void __launch_bounds__(TPB, 4) qsp_eval_kernel(const float* __restrict__ th,
                                                          float* __restrict__ out) {
    __shared__ unsigned long long sc[68];
    int t = threadIdx.x;
    int base_el = (blockIdx.x * TPB + t) * EPT;

    // ---- alpha-independent prework (overlaps coef kernel via PDL) ----
    float4 th4 = *reinterpret_cast<const float4*>(th + base_el);
    unsigned long long VV[EPT];
    float cc[EPT][4], ts[EPT][4];
    const unsigned long long FOUR = 0x4080000040800000ull; // ( 4, 4)
    const unsigned long long NEG2 = 0xC0000000C0000000ull; // (-2,-2)
    const unsigned long long SGN  = 0x8000000080000000ull; // packed negate mask
#pragma unroll
    for (int pr = 0; pr < 2; pr++) {
        float th0 = (pr == 0) ? th4.x : th4.z;
        float th1 = (pr == 0) ? th4.y : th4.w;
        float cv0 = __cosf(th0), sv0 = __sinf(th0);
        float cv1 = __cosf(th1), sv1 = __sinf(th1);
        unsigned long long C  = pk2(cv0, cv1);
        unsigned long long Sn = pk2(sv0, sv1);
        unsigned long long U  = fma2(mul2(C, FOUR), C, NEG2);  // 2cos2t
        unsigned long long W  = fma2(U, U, NEG2);              // 2cos4t
        unsigned long long X8 = fma2(W, W, NEG2);              // 2cos8t
        unsigned long long V  = fma2(X8, X8, NEG2);            // 2cos16t
        unsigned long long c3p = fma2(U, C,   C ^ SGN);        // cos3t
        unsigned long long c5p = fma2(U, c3p, C ^ SGN);        // cos5t
        unsigned long long c7p = fma2(U, c5p, c3p ^ SGN);      // cos7t
        unsigned long long s3p = fma2(U, Sn,  Sn);             // sin3t
        unsigned long long s5p = fma2(U, s3p, Sn ^ SGN);       // sin5t
        unsigned long long s7p = fma2(U, s5p, s3p ^ SGN);      // sin7t
        unsigned long long K   = mul2(mul2(mul2(C, U), W), X8);
        unsigned long long sn  = mul2(Sn, K);   // sin(16t)/2 (2 folded into G)
        unsigned long long t1p = mul2(Sn,  sn);
        unsigned long long t3p = mul2(s3p, sn);
        unsigned long long t5p = mul2(s5p, sn);
        unsigned long long t7p = mul2(s7p, sn);

        int i0 = 2 * pr, i1 = 2 * pr + 1;
        float lo, hi;
        upk2(V, lo, hi);   VV[i0] = pk2(lo, lo); VV[i1] = pk2(hi, hi);
        cc[i0][0] = cv0;   cc[i1][0] = cv1;
        upk2(c3p, lo, hi); cc[i0][1] = lo; cc[i1][1] = hi;
        upk2(c5p, lo, hi); cc[i0][2] = lo; cc[i1][2] = hi;
        upk2(c7p, lo, hi); cc[i0][3] = lo; cc[i1][3] = hi;
        upk2(t1p, lo, hi); ts[i0][0] = lo; ts[i1][0] = hi;
        upk2(t3p, lo, hi); ts[i0][1] = lo; ts[i1][1] = hi;
        upk2(t5p, lo, hi); ts[i0][2] = lo; ts[i1][2] = hi;
        upk2(t7p, lo, hi); ts[i0][3] = lo; ts[i1][3] = hi;
    }

    // ---- acquire coefficient publication, then stage into shared ----
    if (t == 0) {
        unsigned f;
        for (;;) {
            asm volatile("ld.acquire.gpu.global.u32 %0, [%1];"
                         : "=r"(f) : "l"(&g_flag));
            if (f) break;
            __nanosleep(64);
        }
    }
    __syncthreads();
    if (t < 68) sc[t] = g_coef[t];
    __syncthreads();

    unsigned long long b[EPT][4];
    unsigned long long S[EPT];

    // ---- F phase ----
#pragma unroll
    for (int i = 0; i < EPT; i++)
#pragma unroll
        for (int s = 0; s < 4; s++)
            b[i][s] = sc[s * 9 + 8];
#pragma unroll
    for (int p = 7; p >= 0; p--) {
#pragma unroll
        for (int s = 0; s < 4; s++) {
            unsigned long long cf = sc[s * 9 + p];
#pragma unroll
            for (int i = 0; i < EPT; i++)
                b[i][s] = fma2(VV[i], b[i][s], cf);
        }
    }
#pragma unroll
    for (int i = 0; i < EPT; i++) {
        S[i] = mul2(pk2(cc[i][0], cc[i][0]), b[i][0]);
#pragma unroll
        for (int s = 1; s < 4; s++)
            S[i] = fma2(pk2(cc[i][s], cc[i][s]), b[i][s], S[i]);
    }

    // ---- G phase (reuses b registers) ----
#pragma unroll
    for (int i = 0; i < EPT; i++)
#pragma unroll
        for (int s = 0; s < 4; s++)
            b[i][s] = sc[36 + s * 8 + 7];
#pragma unroll
    for (int p = 6; p >= 0; p--) {
#pragma unroll
        for (int s = 0; s < 4; s++) {
            unsigned long long cf = sc[36 + s * 8 + p];
#pragma unroll
            for (int i = 0; i < EPT; i++)
                b[i][s] = fma2(VV[i], b[i][s], cf);
        }
    }

    float4 re, im;
#pragma unroll
    for (int i = 0; i < EPT; i++) {
#pragma unroll
        for (int s = 0; s < 4; s++)
            S[i] = fma2(pk2(ts[i][s], ts[i][s]), b[i][s], S[i]);
        float r, q;
        upk2(S[i], r, q);
        (&re.x)[i] = r;
        (&im.x)[i] = q;
    }

    *reinterpret_cast<float4*>(out + base_el)           = re;
    *reinterpret_cast<float4*>(out + B_TOTAL + base_el) = im;
}

// ---------------- Launch ----------------
extern "C" void kernel_launch(void* const* d_in, const int* in_sizes, int n_in,
                              void* d_out, int out_size) {
    const float* th   = (const float*)d_in[0];
    const float* phis = (const float*)d_in[1];
    if (n_in >= 2 && in_sizes[0] == NPHI) {
        phis = (const float*)d_in[0];
        th   = (const float*)d_in[1];
    }
    float* out = (float*)d_out;

    qsp_coef_kernel<<<1, TPB_COEF>>>(phis);

    // Eval with Programmatic Dependent Launch: starts while coef runs, does
    // trig prework, then acquire-spins on the flag before reading g_coef.
    cudaLaunchConfig_t cfg = {};
    cfg.gridDim  = dim3(B_TOTAL / EPT / TPB);   // 2048
    cfg.blockDim = dim3(TPB);
    cfg.dynamicSmemBytes = 0;
    cfg.stream = 0;
    cudaLaunchAttribute attrs[1];
    attrs[0].id = cudaLaunchAttributeProgrammaticStreamSerialization;
    attrs[0].val.programmaticStreamSerializationAllowed = 1;
    cfg.attrs = attrs;
    cfg.numAttrs = 1;
    cudaLaunchKernelEx(&cfg, qsp_eval_kernel, th, out);
}